// round 12
// baseline (speedup 1.0000x reference)
#include <cuda_runtime.h>
#include <cuda_bf16.h>
#include <math.h>
#include <stdint.h>

// Problem constants: B=2, T=2048, C=1024, H=16, D=64
typedef __nv_bfloat16 bf16;

// pre-split bf16 hi/lo planes
__device__ __align__(256) bf16 g_Xh[4096u * 1024], g_Xl[4096u * 1024];   // x [B*T, C]
__device__ __align__(256) bf16 g_Wh[3072u * 1024], g_Wl[3072u * 1024];   // qkv_w
__device__ __align__(256) bf16 g_Uh[1024u * 1024], g_Ul[1024u * 1024];   // out_w
__device__ __align__(256) bf16 g_Qh[4194304], g_Ql[4194304];             // [B,H,T,D]
__device__ __align__(256) bf16 g_Kh[4194304], g_Kl[4194304];
__device__ __align__(256) bf16 g_Vh[4194304], g_Vl[4194304];
__device__ __align__(256) bf16 g_Oh[4096u * 1024], g_Ol[4096u * 1024];   // [B,T,C]

// ---------------------------------------------------------------------------
__device__ __forceinline__ void bfsplit(float x, bf16& h, bf16& l) {
    h = __float2bfloat16(x);
    l = __float2bfloat16(x - __bfloat162float(h));
}
__device__ __forceinline__ void split4(bf16* ph, bf16* pl, float4 v) {
    bf16 h[4], l[4];
    bfsplit(v.x, h[0], l[0]); bfsplit(v.y, h[1], l[1]);
    bfsplit(v.z, h[2], l[2]); bfsplit(v.w, h[3], l[3]);
    *(uint2*)ph = *(const uint2*)h;
    *(uint2*)pl = *(const uint2*)l;
}
__device__ __forceinline__ uint32_t packsplit(float a, float b, uint32_t& lo) {
    union { bf16 h[2]; uint32_t u; } hw, lw;
    bfsplit(a, hw.h[0], lw.h[0]);
    bfsplit(b, hw.h[1], lw.h[1]);
    lo = lw.u;
    return hw.u;
}
__device__ __forceinline__ void mma16(float* d, const uint32_t* a, const uint32_t* b) {
    asm volatile(
        "mma.sync.aligned.m16n8k16.row.col.f32.bf16.bf16.f32 "
        "{%0,%1,%2,%3},{%4,%5,%6,%7},{%8,%9},{%0,%1,%2,%3};"
        : "+f"(d[0]), "+f"(d[1]), "+f"(d[2]), "+f"(d[3])
        : "r"(a[0]), "r"(a[1]), "r"(a[2]), "r"(a[3]), "r"(b[0]), "r"(b[1]));
}
__device__ __forceinline__ uint32_t sptr(const void* p) {
    return (uint32_t)__cvta_generic_to_shared(p);
}
__device__ __forceinline__ void ldsm_x4(uint32_t* r, uint32_t a) {
    asm volatile("ldmatrix.sync.aligned.m8n8.x4.shared.b16 {%0,%1,%2,%3}, [%4];"
                 : "=r"(r[0]), "=r"(r[1]), "=r"(r[2]), "=r"(r[3]) : "r"(a));
}
__device__ __forceinline__ void ldsm_x2(uint32_t* r, uint32_t a) {
    asm volatile("ldmatrix.sync.aligned.m8n8.x2.shared.b16 {%0,%1}, [%2];"
                 : "=r"(r[0]), "=r"(r[1]) : "r"(a));
}
__device__ __forceinline__ void ldsm_x2t(uint32_t* r, uint32_t a) {
    asm volatile("ldmatrix.sync.aligned.m8n8.x2.trans.shared.b16 {%0,%1}, [%2];"
                 : "=r"(r[0]), "=r"(r[1]) : "r"(a));
}

// ---------------------------------------------------------------------------
// presplit: fp32 -> bf16 hi/lo planes
// ---------------------------------------------------------------------------
__global__ void presplit(const float* __restrict__ src, bf16* __restrict__ h,
                         bf16* __restrict__ l, int n4)
{
    int i = blockIdx.x * blockDim.x + threadIdx.x;
    if (i < n4) split4(h + 4 * i, l + 4 * i, ((const float4*)src)[i]);
}

// ---------------------------------------------------------------------------
// 3xBF16-split GEMM on pre-split inputs (unchanged from R11 win).
// Block 128(m) x 256(n), BK=16, 8 warps, warp tile 64x64.
// ---------------------------------------------------------------------------
#define GS 24
#define STG_A (128 * GS)
#define STG_B (256 * GS)
#define STG_ELEMS (2 * STG_A + 2 * STG_B)
#define GEMM_SMEM (2 * STG_ELEMS * 2)       // 73,728 B

template <int MODE>
__global__ void __launch_bounds__(256, 1) gemm_pre(
    const bf16* __restrict__ Ah_g, const bf16* __restrict__ Al_g,
    const bf16* __restrict__ Bh_g, const bf16* __restrict__ Bl_g,
    const float* __restrict__ bias, float* __restrict__ Out)
{
    extern __shared__ bf16 gsm[];
    const int tid = threadIdx.x;
    const int m0 = blockIdx.y * 128, n0 = blockIdx.x * 256;
    const int warp = tid >> 5, lane = tid & 31;
    const int wm = (warp >> 2) * 64, wn = (warp & 3) * 64;
    const int g = lane >> 2, tq = lane & 3;
    const int lrow16 = lane & 15, lc8 = ((lane >> 4) & 1) * 8;
    const int brow = lane & 7, bc8 = ((lane >> 3) & 1) * 8;

    const bf16* gsrc[6];
    uint32_t soff[6];
#pragma unroll
    for (int j = 0; j < 6; j++) {
        int id = tid + j * 256;
        if (id < 512) {
            int pl = id >> 8, row = (id >> 1) & 127, hf = id & 1;
            gsrc[j] = (pl ? Al_g : Ah_g) + (size_t)(m0 + row) * 1024 + hf * 8;
            soff[j] = pl * STG_A + row * GS + hf * 8;
        } else {
            int id2 = id - 512;
            int pl = id2 >> 9, row = (id2 >> 1) & 255, hf = id2 & 1;
            gsrc[j] = (pl ? Bl_g : Bh_g) + (size_t)(n0 + row) * 1024 + hf * 8;
            soff[j] = 2 * STG_A + pl * STG_B + row * GS + hf * 8;
        }
    }

    float acc[4][8][4];
#pragma unroll
    for (int mt = 0; mt < 4; mt++)
#pragma unroll
        for (int nt = 0; nt < 8; nt++)
#pragma unroll
            for (int r = 0; r < 4; r++) acc[mt][nt][r] = 0.f;

    uint4 rg[6];
#pragma unroll
    for (int j = 0; j < 6; j++) rg[j] = *(const uint4*)gsrc[j];
#pragma unroll
    for (int j = 0; j < 6; j++) *(uint4*)&gsm[soff[j]] = rg[j];
#pragma unroll
    for (int j = 0; j < 6; j++) rg[j] = *(const uint4*)(gsrc[j] + 16);
    __syncthreads();

    for (int kt = 0; kt < 64; kt++) {
        const int buf = kt & 1;
        if (kt < 63) {
            const uint32_t sb = (buf ^ 1) * STG_ELEMS;
#pragma unroll
            for (int j = 0; j < 6; j++) *(uint4*)&gsm[sb + soff[j]] = rg[j];
        }
        if (kt < 62) {
#pragma unroll
            for (int j = 0; j < 6; j++) rg[j] = *(const uint4*)(gsrc[j] + (kt + 2) * 16);
        }
        bf16* Ah = gsm + buf * STG_ELEMS;
        bf16* Al = Ah + STG_A;
        bf16* Bh = Ah + 2 * STG_A;
        bf16* Bl = Bh + STG_B;

        uint32_t Ahf[4][4], Alf[4][4];
#pragma unroll
        for (int mt = 0; mt < 4; mt++) {
            int r0 = (wm + mt * 16 + lrow16) * GS + lc8;
            ldsm_x4(Ahf[mt], sptr(&Ah[r0]));
            ldsm_x4(Alf[mt], sptr(&Al[r0]));
        }
#pragma unroll
        for (int nh = 0; nh < 2; nh++) {
            uint32_t Bhf[4][2], Blf[4][2];
#pragma unroll
            for (int j = 0; j < 4; j++) {
                int c0r = (wn + (nh * 4 + j) * 8 + brow) * GS + bc8;
                ldsm_x2(Bhf[j], sptr(&Bh[c0r]));
                ldsm_x2(Blf[j], sptr(&Bl[c0r]));
            }
#pragma unroll
            for (int mt = 0; mt < 4; mt++)
#pragma unroll
                for (int j = 0; j < 4; j++) {
                    float* d = acc[mt][nh * 4 + j];
                    mma16(d, Ahf[mt], Bhf[j]);
                    mma16(d, Alf[mt], Bhf[j]);
                    mma16(d, Ahf[mt], Blf[j]);
                }
        }
        if (kt < 63) __syncthreads();
    }

#pragma unroll
    for (int mt = 0; mt < 4; mt++) {
#pragma unroll
        for (int rr = 0; rr < 2; rr++) {
            int m = m0 + wm + mt * 16 + g + rr * 8;
#pragma unroll
            for (int nt = 0; nt < 8; nt++) {
                int n = n0 + wn + nt * 8 + tq * 2;
                float v0 = acc[mt][nt][rr * 2] + bias[n];
                float v1 = acc[mt][nt][rr * 2 + 1] + bias[n + 1];
                if (MODE == 0) {
                    int bb = m >> 11, tt = m & 2047;
                    int which = n >> 10, c = n & 1023, hh = c >> 6, dd = c & 63;
                    bf16 *dh, *dl;
                    if (which == 0) { dh = g_Qh; dl = g_Ql; }
                    else if (which == 1) { dh = g_Kh; dl = g_Kl; }
                    else { dh = g_Vh; dl = g_Vl; }
                    size_t off = (((size_t)bb * 16 + hh) * 2048 + tt) * 64 + dd;
                    uint32_t lo, hi = packsplit(v0, v1, lo);
                    *(uint32_t*)&dh[off] = hi;
                    *(uint32_t*)&dl[off] = lo;
                } else {
                    *(float2*)&Out[(size_t)m * 1024 + n] = make_float2(v0, v1);
                }
            }
        }
    }
}

// ---------------------------------------------------------------------------
// Flash attention. Block 256 thr (8 warps), 256 q-rows, warp q-tile 32.
// NEW: P kept in registers (exp'd S-fragments ARE the PV A-fragments);
// K/V double-buffered, one __syncthreads per kt.
// ---------------------------------------------------------------------------
#define AS 72
#define QPL (256 * AS)            // per Q plane
#define KVPL (64 * AS)            // per K/V plane
#define KVT (4 * KVPL)            // one KV tile: Kh,Kl,Vh,Vl
#define ATTN_SMEM ((2 * QPL + 2 * KVT) * 2)  // 147,456 B

__global__ void __launch_bounds__(256) attn_pre()
{
    extern __shared__ bf16 smb[];
    bf16* Qh = smb;
    bf16* Ql = smb + QPL;

    const int tid = threadIdx.x;
    const int qt = gridDim.x - 1 - blockIdx.x;   // heavy blocks first
    const int bh = blockIdx.y;
    const int Q0 = qt * 256;
    const size_t hbase = (size_t)bh * 2048 * 64;

    const int warp = tid >> 5, lane = tid & 31;
    const int g = lane >> 2, tq = lane & 3;
    const int lqb = warp * 32;
    const int qwmin = Q0 + lqb;
    const int lrow16 = lane & 15, lc8 = ((lane >> 4) & 1) * 8;
    const int brow = lane & 7, bc8 = ((lane >> 3) & 1) * 8;

    // load Q planes [256][64] -> [256][AS]
#pragma unroll
    for (int j = 0; j < 16; j++) {
        int id = tid + j * 256;
        int pl = id >> 11, r = (id >> 3) & 255, c = id & 7;
        const bf16* src = (pl ? g_Ql : g_Qh) + hbase + (size_t)(Q0 + r) * 64 + c * 8;
        *(uint4*)&smb[pl * QPL + r * AS + c * 8] = *(const uint4*)src;
    }

    // KV copy plan: 8 chunks/thread; sel 0..3 = Kh,Kl,Vh,Vl; offsets relative to tile
    const bf16* kvsrc[8];
    uint32_t kvoff[8];
#pragma unroll
    for (int j = 0; j < 8; j++) {
        int id = tid + j * 256;
        int sel = id >> 9, r = (id >> 3) & 63, c = id & 7;
        const bf16* base = (sel == 0) ? g_Kh : (sel == 1) ? g_Kl : (sel == 2) ? g_Vh : g_Vl;
        kvsrc[j] = base + hbase + (size_t)r * 64 + c * 8;
        kvoff[j] = sel * KVPL + r * AS + c * 8;
    }
    // prologue: stage KV tile 0 into buf 0
    {
        bf16* dst = smb + 2 * QPL;
#pragma unroll
        for (int j = 0; j < 8; j++) *(uint4*)&dst[kvoff[j]] = *(const uint4*)kvsrc[j];
    }

    float ofrag[2][8][4];
#pragma unroll
    for (int mt = 0; mt < 2; mt++)
#pragma unroll
        for (int nt = 0; nt < 8; nt++)
#pragma unroll
            for (int r = 0; r < 4; r++) ofrag[mt][nt][r] = 0.f;
    float mrow[2][2], lrow[2][2];
#pragma unroll
    for (int mt = 0; mt < 2; mt++)
#pragma unroll
        for (int r = 0; r < 2; r++) { mrow[mt][r] = -INFINITY; lrow[mt][r] = 0.f; }

    const int ktmax = 4 * qt + 3;
    for (int kt = 0; kt <= ktmax; kt++) {
        __syncthreads();  // makes buf(kt&1) stores visible; prior buf^1 readers done
        if (kt < ktmax) {
            bf16* dst = smb + 2 * QPL + ((kt + 1) & 1) * KVT;
#pragma unroll
            for (int j = 0; j < 8; j++)
                *(uint4*)&dst[kvoff[j]] = *(const uint4*)(kvsrc[j] + (size_t)(kt + 1) * 4096);
        }
        bf16* Kh = smb + 2 * QPL + (kt & 1) * KVT;
        bf16* Kl = Kh + KVPL;
        bf16* Vh = Kh + 2 * KVPL;
        bf16* Vl = Kh + 3 * KVPL;

        const int k0g = kt * 64;
        if (k0g > qwmin + 31) continue;
        const bool needmask = (k0g + 63 > qwmin);

        // S = Q K^T
        float sfrag[2][8][4];
#pragma unroll
        for (int mt = 0; mt < 2; mt++)
#pragma unroll
            for (int nt = 0; nt < 8; nt++)
#pragma unroll
                for (int r = 0; r < 4; r++) sfrag[mt][nt][r] = 0.f;

#pragma unroll
        for (int k16 = 0; k16 < 4; k16++) {
            int kb = k16 * 16;
            uint32_t ah[2][4], al[2][4];
#pragma unroll
            for (int mt = 0; mt < 2; mt++) {
                int r0 = (lqb + mt * 16 + lrow16) * AS + kb + lc8;
                ldsm_x4(ah[mt], sptr(&Qh[r0]));
                ldsm_x4(al[mt], sptr(&Ql[r0]));
            }
#pragma unroll
            for (int nt = 0; nt < 8; nt++) {
                int nr = (nt * 8 + brow) * AS + kb + bc8;
                uint32_t bh2[2], bl2[2];
                ldsm_x2(bh2, sptr(&Kh[nr]));
                ldsm_x2(bl2, sptr(&Kl[nr]));
#pragma unroll
                for (int mt = 0; mt < 2; mt++) {
                    mma16(sfrag[mt][nt], ah[mt], bh2);
                    mma16(sfrag[mt][nt], al[mt], bh2);
                    mma16(sfrag[mt][nt], ah[mt], bl2);
                }
            }
        }

        // softmax on fragments; pack P (hi/lo) into registers
        uint32_t pfh[2][8][2], pfl[2][8][2];
#pragma unroll
        for (int mt = 0; mt < 2; mt++) {
#pragma unroll
            for (int r = 0; r < 2; r++) {
                int lq = lqb + mt * 16 + r * 8 + g;
                int qglob = Q0 + lq;
                float rm = -INFINITY;
#pragma unroll
                for (int nt = 0; nt < 8; nt++) {
#pragma unroll
                    for (int cc = 0; cc < 2; cc++) {
                        float sv = sfrag[mt][nt][r * 2 + cc] * 0.125f;
                        int keyg = k0g + nt * 8 + tq * 2 + cc;
                        if (needmask && keyg > qglob) sv = -INFINITY;
                        sfrag[mt][nt][r * 2 + cc] = sv;
                        rm = fmaxf(rm, sv);
                    }
                }
                rm = fmaxf(rm, __shfl_xor_sync(0xffffffffu, rm, 1));
                rm = fmaxf(rm, __shfl_xor_sync(0xffffffffu, rm, 2));
                float mnew = fmaxf(mrow[mt][r], rm);
                float esc = __expf(mrow[mt][r] - mnew);
                float rs = 0.f;
#pragma unroll
                for (int nt = 0; nt < 8; nt++) {
                    float p0 = __expf(sfrag[mt][nt][r * 2] - mnew);
                    float p1 = __expf(sfrag[mt][nt][r * 2 + 1] - mnew);
                    pfh[mt][nt][r] = packsplit(p0, p1, pfl[mt][nt][r]);
                    rs += p0 + p1;
                }
                rs += __shfl_xor_sync(0xffffffffu, rs, 1);
                rs += __shfl_xor_sync(0xffffffffu, rs, 2);
                lrow[mt][r] = lrow[mt][r] * esc + rs;
                mrow[mt][r] = mnew;
#pragma unroll
                for (int nt = 0; nt < 8; nt++) {
                    ofrag[mt][nt][r * 2] *= esc;
                    ofrag[mt][nt][r * 2 + 1] *= esc;
                }
            }
        }

        // O += P V  (P A-fragments straight from registers; V via ldmatrix.trans)
#pragma unroll
        for (int j = 0; j < 4; j++) {
            int kb = j * 16;
#pragma unroll
            for (int nt = 0; nt < 8; nt++) {
                int vr = (kb + lrow16) * AS + nt * 8;
                uint32_t bh2[2], bl2[2];
                ldsm_x2t(bh2, sptr(&Vh[vr]));
                ldsm_x2t(bl2, sptr(&Vl[vr]));
#pragma unroll
                for (int mt = 0; mt < 2; mt++) {
                    uint32_t ah[4] = {pfh[mt][2 * j][0], pfh[mt][2 * j][1],
                                      pfh[mt][2 * j + 1][0], pfh[mt][2 * j + 1][1]};
                    uint32_t al[4] = {pfl[mt][2 * j][0], pfl[mt][2 * j][1],
                                      pfl[mt][2 * j + 1][0], pfl[mt][2 * j + 1][1]};
                    mma16(ofrag[mt][nt], ah, bh2);
                    mma16(ofrag[mt][nt], al, bh2);
                    mma16(ofrag[mt][nt], ah, bl2);
                }
            }
        }
    }

    // normalize + write O hi/lo planes [B,T,C]
    const int b = bh >> 4, h = bh & 15;
#pragma unroll
    for (int mt = 0; mt < 2; mt++) {
#pragma unroll
        for (int r = 0; r < 2; r++) {
            float inv = 1.f / lrow[mt][r];
            int q = Q0 + lqb + mt * 16 + r * 8 + g;
#pragma unroll
            for (int nt = 0; nt < 8; nt++) {
                size_t off = ((size_t)b * 2048 + q) * 1024 + h * 64 + nt * 8 + tq * 2;
                uint32_t lo, hi = packsplit(ofrag[mt][nt][r * 2] * inv,
                                            ofrag[mt][nt][r * 2 + 1] * inv, lo);
                *(uint32_t*)&g_Oh[off] = hi;
                *(uint32_t*)&g_Ol[off] = lo;
            }
        }
    }
}

// ---------------------------------------------------------------------------
extern "C" void kernel_launch(void* const* d_in, const int* in_sizes, int n_in,
                              void* d_out, int out_size)
{
    const float* x     = (const float*)d_in[0];
    const float* qkv_w = (const float*)d_in[1];
    const float* qkv_b = (const float*)d_in[2];
    const float* out_w = (const float*)d_in[3];
    const float* out_b = (const float*)d_in[4];
    float* out = (float*)d_out;

    bf16 *xh, *xl, *wh, *wl, *uh, *ul, *oh, *ol;
    cudaGetSymbolAddress((void**)&xh, g_Xh); cudaGetSymbolAddress((void**)&xl, g_Xl);
    cudaGetSymbolAddress((void**)&wh, g_Wh); cudaGetSymbolAddress((void**)&wl, g_Wl);
    cudaGetSymbolAddress((void**)&uh, g_Uh); cudaGetSymbolAddress((void**)&ul, g_Ul);
    cudaGetSymbolAddress((void**)&oh, g_Oh); cudaGetSymbolAddress((void**)&ol, g_Ol);

    presplit<<<4096, 256>>>(x, xh, xl, 4096 * 1024 / 4);
    presplit<<<3072, 256>>>(qkv_w, wh, wl, 3072 * 1024 / 4);
    presplit<<<1024, 256>>>(out_w, uh, ul, 1024 * 1024 / 4);

    cudaFuncSetAttribute(gemm_pre<0>, cudaFuncAttributeMaxDynamicSharedMemorySize, GEMM_SMEM);
    cudaFuncSetAttribute(gemm_pre<1>, cudaFuncAttributeMaxDynamicSharedMemorySize, GEMM_SMEM);
    cudaFuncSetAttribute(attn_pre, cudaFuncAttributeMaxDynamicSharedMemorySize, ATTN_SMEM);

    gemm_pre<0><<<dim3(12, 32), 256, GEMM_SMEM>>>(xh, xl, wh, wl, qkv_b, nullptr);
    attn_pre<<<dim3(8, 32), 256, ATTN_SMEM>>>();
    gemm_pre<1><<<dim3(4, 32), 256, GEMM_SMEM>>>(oh, ol, uh, ul, out_b, out);
}

// round 13
// speedup vs baseline: 1.0320x; 1.0320x over previous
#include <cuda_runtime.h>
#include <cuda_bf16.h>
#include <math.h>
#include <stdint.h>

// Problem constants: B=2, T=2048, C=1024, H=16, D=64
typedef __nv_bfloat16 bf16;

// pre-split bf16 hi/lo planes
__device__ __align__(256) bf16 g_Xh[4096u * 1024], g_Xl[4096u * 1024];   // x [B*T, C]
__device__ __align__(256) bf16 g_Wh[3072u * 1024], g_Wl[3072u * 1024];   // qkv_w
__device__ __align__(256) bf16 g_Uh[1024u * 1024], g_Ul[1024u * 1024];   // out_w
__device__ __align__(256) bf16 g_Qh[4194304], g_Ql[4194304];             // [B,H,T,D]
__device__ __align__(256) bf16 g_Kh[4194304], g_Kl[4194304];
__device__ __align__(256) bf16 g_Vh[4194304], g_Vl[4194304];
__device__ __align__(256) bf16 g_Oh[4096u * 1024], g_Ol[4096u * 1024];   // [B,T,C]

// ---------------------------------------------------------------------------
__device__ __forceinline__ void bfsplit(float x, bf16& h, bf16& l) {
    h = __float2bfloat16(x);
    l = __float2bfloat16(x - __bfloat162float(h));
}
__device__ __forceinline__ void split4(bf16* ph, bf16* pl, float4 v) {
    bf16 h[4], l[4];
    bfsplit(v.x, h[0], l[0]); bfsplit(v.y, h[1], l[1]);
    bfsplit(v.z, h[2], l[2]); bfsplit(v.w, h[3], l[3]);
    *(uint2*)ph = *(const uint2*)h;
    *(uint2*)pl = *(const uint2*)l;
}
__device__ __forceinline__ uint32_t packsplit(float a, float b, uint32_t& lo) {
    union { bf16 h[2]; uint32_t u; } hw, lw;
    bfsplit(a, hw.h[0], lw.h[0]);
    bfsplit(b, hw.h[1], lw.h[1]);
    lo = lw.u;
    return hw.u;
}
__device__ __forceinline__ void mma16(float* d, const uint32_t* a, const uint32_t* b) {
    asm volatile(
        "mma.sync.aligned.m16n8k16.row.col.f32.bf16.bf16.f32 "
        "{%0,%1,%2,%3},{%4,%5,%6,%7},{%8,%9},{%0,%1,%2,%3};"
        : "+f"(d[0]), "+f"(d[1]), "+f"(d[2]), "+f"(d[3])
        : "r"(a[0]), "r"(a[1]), "r"(a[2]), "r"(a[3]), "r"(b[0]), "r"(b[1]));
}
__device__ __forceinline__ uint32_t sptr(const void* p) {
    return (uint32_t)__cvta_generic_to_shared(p);
}
__device__ __forceinline__ void ldsm_x4(uint32_t* r, uint32_t a) {
    asm volatile("ldmatrix.sync.aligned.m8n8.x4.shared.b16 {%0,%1,%2,%3}, [%4];"
                 : "=r"(r[0]), "=r"(r[1]), "=r"(r[2]), "=r"(r[3]) : "r"(a));
}
__device__ __forceinline__ void ldsm_x2(uint32_t* r, uint32_t a) {
    asm volatile("ldmatrix.sync.aligned.m8n8.x2.shared.b16 {%0,%1}, [%2];"
                 : "=r"(r[0]), "=r"(r[1]) : "r"(a));
}
__device__ __forceinline__ void ldsm_x2t(uint32_t* r, uint32_t a) {
    asm volatile("ldmatrix.sync.aligned.m8n8.x2.trans.shared.b16 {%0,%1}, [%2];"
                 : "=r"(r[0]), "=r"(r[1]) : "r"(a));
}

// ---------------------------------------------------------------------------
// presplit: fp32 -> bf16 hi/lo planes
// ---------------------------------------------------------------------------
__global__ void presplit(const float* __restrict__ src, bf16* __restrict__ h,
                         bf16* __restrict__ l, int n4)
{
    int i = blockIdx.x * blockDim.x + threadIdx.x;
    if (i < n4) split4(h + 4 * i, l + 4 * i, ((const float4*)src)[i]);
}

// ---------------------------------------------------------------------------
// 3xBF16-split GEMM on pre-split inputs (unchanged from R11 win).
// Block 128(m) x 256(n), BK=16, 8 warps, warp tile 64x64.
// ---------------------------------------------------------------------------
#define GS 24
#define STG_A (128 * GS)
#define STG_B (256 * GS)
#define STG_ELEMS (2 * STG_A + 2 * STG_B)
#define GEMM_SMEM (2 * STG_ELEMS * 2)       // 73,728 B

template <int MODE>
__global__ void __launch_bounds__(256, 1) gemm_pre(
    const bf16* __restrict__ Ah_g, const bf16* __restrict__ Al_g,
    const bf16* __restrict__ Bh_g, const bf16* __restrict__ Bl_g,
    const float* __restrict__ bias, float* __restrict__ Out)
{
    extern __shared__ bf16 gsm[];
    const int tid = threadIdx.x;
    const int m0 = blockIdx.y * 128, n0 = blockIdx.x * 256;
    const int warp = tid >> 5, lane = tid & 31;
    const int wm = (warp >> 2) * 64, wn = (warp & 3) * 64;
    const int g = lane >> 2, tq = lane & 3;
    const int lrow16 = lane & 15, lc8 = ((lane >> 4) & 1) * 8;
    const int brow = lane & 7, bc8 = ((lane >> 3) & 1) * 8;

    const bf16* gsrc[6];
    uint32_t soff[6];
#pragma unroll
    for (int j = 0; j < 6; j++) {
        int id = tid + j * 256;
        if (id < 512) {
            int pl = id >> 8, row = (id >> 1) & 127, hf = id & 1;
            gsrc[j] = (pl ? Al_g : Ah_g) + (size_t)(m0 + row) * 1024 + hf * 8;
            soff[j] = pl * STG_A + row * GS + hf * 8;
        } else {
            int id2 = id - 512;
            int pl = id2 >> 9, row = (id2 >> 1) & 255, hf = id2 & 1;
            gsrc[j] = (pl ? Bl_g : Bh_g) + (size_t)(n0 + row) * 1024 + hf * 8;
            soff[j] = 2 * STG_A + pl * STG_B + row * GS + hf * 8;
        }
    }

    float acc[4][8][4];
#pragma unroll
    for (int mt = 0; mt < 4; mt++)
#pragma unroll
        for (int nt = 0; nt < 8; nt++)
#pragma unroll
            for (int r = 0; r < 4; r++) acc[mt][nt][r] = 0.f;

    uint4 rg[6];
#pragma unroll
    for (int j = 0; j < 6; j++) rg[j] = *(const uint4*)gsrc[j];
#pragma unroll
    for (int j = 0; j < 6; j++) *(uint4*)&gsm[soff[j]] = rg[j];
#pragma unroll
    for (int j = 0; j < 6; j++) rg[j] = *(const uint4*)(gsrc[j] + 16);
    __syncthreads();

    for (int kt = 0; kt < 64; kt++) {
        const int buf = kt & 1;
        if (kt < 63) {
            const uint32_t sb = (buf ^ 1) * STG_ELEMS;
#pragma unroll
            for (int j = 0; j < 6; j++) *(uint4*)&gsm[sb + soff[j]] = rg[j];
        }
        if (kt < 62) {
#pragma unroll
            for (int j = 0; j < 6; j++) rg[j] = *(const uint4*)(gsrc[j] + (kt + 2) * 16);
        }
        bf16* Ah = gsm + buf * STG_ELEMS;
        bf16* Al = Ah + STG_A;
        bf16* Bh = Ah + 2 * STG_A;
        bf16* Bl = Bh + STG_B;

        uint32_t Ahf[4][4], Alf[4][4];
#pragma unroll
        for (int mt = 0; mt < 4; mt++) {
            int r0 = (wm + mt * 16 + lrow16) * GS + lc8;
            ldsm_x4(Ahf[mt], sptr(&Ah[r0]));
            ldsm_x4(Alf[mt], sptr(&Al[r0]));
        }
#pragma unroll
        for (int nh = 0; nh < 2; nh++) {
            uint32_t Bhf[4][2], Blf[4][2];
#pragma unroll
            for (int j = 0; j < 4; j++) {
                int c0r = (wn + (nh * 4 + j) * 8 + brow) * GS + bc8;
                ldsm_x2(Bhf[j], sptr(&Bh[c0r]));
                ldsm_x2(Blf[j], sptr(&Bl[c0r]));
            }
#pragma unroll
            for (int mt = 0; mt < 4; mt++)
#pragma unroll
                for (int j = 0; j < 4; j++) {
                    float* d = acc[mt][nh * 4 + j];
                    mma16(d, Ahf[mt], Bhf[j]);
                    mma16(d, Alf[mt], Bhf[j]);
                    mma16(d, Ahf[mt], Blf[j]);
                }
        }
        if (kt < 63) __syncthreads();
    }

#pragma unroll
    for (int mt = 0; mt < 4; mt++) {
#pragma unroll
        for (int rr = 0; rr < 2; rr++) {
            int m = m0 + wm + mt * 16 + g + rr * 8;
#pragma unroll
            for (int nt = 0; nt < 8; nt++) {
                int n = n0 + wn + nt * 8 + tq * 2;
                float v0 = acc[mt][nt][rr * 2] + bias[n];
                float v1 = acc[mt][nt][rr * 2 + 1] + bias[n + 1];
                if (MODE == 0) {
                    int bb = m >> 11, tt = m & 2047;
                    int which = n >> 10, c = n & 1023, hh = c >> 6, dd = c & 63;
                    bf16 *dh, *dl;
                    if (which == 0) { dh = g_Qh; dl = g_Ql; }
                    else if (which == 1) { dh = g_Kh; dl = g_Kl; }
                    else { dh = g_Vh; dl = g_Vl; }
                    size_t off = (((size_t)bb * 16 + hh) * 2048 + tt) * 64 + dd;
                    uint32_t lo, hi = packsplit(v0, v1, lo);
                    *(uint32_t*)&dh[off] = hi;
                    *(uint32_t*)&dl[off] = lo;
                } else {
                    *(float2*)&Out[(size_t)m * 1024 + n] = make_float2(v0, v1);
                }
            }
        }
    }
}

// ---------------------------------------------------------------------------
// Flash attention (R11 structure; ONLY change: K/V double-buffered, one
// __syncthreads per kt). Block 256 thr (8 warps), 256 q-rows, warp q-tile 32.
// P goes through smem planes (R11 path). K [key][k]; V natural via ldsm.trans.
// ---------------------------------------------------------------------------
#define AS 72
#define QPL (256 * AS)            // per Q/P plane
#define KVPL (64 * AS)            // per K/V plane
#define KVT (4 * KVPL)            // one KV tile: Kh,Kl,Vh,Vl
// layout: Qh | Ql | KVbuf0 | KVbuf1 | Ph | Pl
#define ATTN_SMEM ((4 * QPL + 2 * KVT) * 2)  // 221,184 B

__global__ void __launch_bounds__(256) attn_pre()
{
    extern __shared__ bf16 smb[];
    bf16* Qh = smb;
    bf16* Ql = smb + QPL;
    bf16* Ph = smb + 2 * QPL + 2 * KVT;
    bf16* Pl = Ph + QPL;

    const int tid = threadIdx.x;
    const int qt = gridDim.x - 1 - blockIdx.x;   // heavy blocks first
    const int bh = blockIdx.y;
    const int Q0 = qt * 256;
    const size_t hbase = (size_t)bh * 2048 * 64;

    const int warp = tid >> 5, lane = tid & 31;
    const int g = lane >> 2, tq = lane & 3;
    const int lqb = warp * 32;
    const int qwmin = Q0 + lqb;
    const int lrow16 = lane & 15, lc8 = ((lane >> 4) & 1) * 8;
    const int brow = lane & 7, bc8 = ((lane >> 3) & 1) * 8;

    // load Q planes [256][64] -> [256][AS]
#pragma unroll
    for (int j = 0; j < 16; j++) {
        int id = tid + j * 256;
        int pl = id >> 11, r = (id >> 3) & 255, c = id & 7;
        const bf16* src = (pl ? g_Ql : g_Qh) + hbase + (size_t)(Q0 + r) * 64 + c * 8;
        *(uint4*)&smb[pl * QPL + r * AS + c * 8] = *(const uint4*)src;
    }

    // KV copy plan: 8 chunks/thread; sel 0..3 = Kh,Kl,Vh,Vl; offsets tile-relative
    const bf16* kvsrc[8];
    uint32_t kvoff[8];
#pragma unroll
    for (int j = 0; j < 8; j++) {
        int id = tid + j * 256;
        int sel = id >> 9, r = (id >> 3) & 63, c = id & 7;
        const bf16* base = (sel == 0) ? g_Kh : (sel == 1) ? g_Kl : (sel == 2) ? g_Vh : g_Vl;
        kvsrc[j] = base + hbase + (size_t)r * 64 + c * 8;
        kvoff[j] = sel * KVPL + r * AS + c * 8;
    }
    // prologue: stage KV tile 0 into buf 0
    {
        bf16* dst = smb + 2 * QPL;
#pragma unroll
        for (int j = 0; j < 8; j++) *(uint4*)&dst[kvoff[j]] = *(const uint4*)kvsrc[j];
    }

    float ofrag[2][8][4];
#pragma unroll
    for (int mt = 0; mt < 2; mt++)
#pragma unroll
        for (int nt = 0; nt < 8; nt++)
#pragma unroll
            for (int r = 0; r < 4; r++) ofrag[mt][nt][r] = 0.f;
    float mrow[2][2], lrow[2][2];
#pragma unroll
    for (int mt = 0; mt < 2; mt++)
#pragma unroll
        for (int r = 0; r < 2; r++) { mrow[mt][r] = -INFINITY; lrow[mt][r] = 0.f; }

    const int ktmax = 4 * qt + 3;
    for (int kt = 0; kt <= ktmax; kt++) {
        __syncthreads();  // publishes buf(kt&1); prior readers of buf^1 are done
        if (kt < ktmax) {
            bf16* dst = smb + 2 * QPL + ((kt + 1) & 1) * KVT;
#pragma unroll
            for (int j = 0; j < 8; j++)
                *(uint4*)&dst[kvoff[j]] = *(const uint4*)(kvsrc[j] + (size_t)(kt + 1) * 4096);
        }
        bf16* Kh = smb + 2 * QPL + (kt & 1) * KVT;
        bf16* Kl = Kh + KVPL;
        bf16* Vh = Kh + 2 * KVPL;
        bf16* Vl = Kh + 3 * KVPL;

        const int k0g = kt * 64;
        if (k0g > qwmin + 31) continue;
        const bool needmask = (k0g + 63 > qwmin);

        // S = Q K^T
        float sfrag[2][8][4];
#pragma unroll
        for (int mt = 0; mt < 2; mt++)
#pragma unroll
            for (int nt = 0; nt < 8; nt++)
#pragma unroll
                for (int r = 0; r < 4; r++) sfrag[mt][nt][r] = 0.f;

#pragma unroll
        for (int k16 = 0; k16 < 4; k16++) {
            int kb = k16 * 16;
            uint32_t ah[2][4], al[2][4];
#pragma unroll
            for (int mt = 0; mt < 2; mt++) {
                int r0 = (lqb + mt * 16 + lrow16) * AS + kb + lc8;
                ldsm_x4(ah[mt], sptr(&Qh[r0]));
                ldsm_x4(al[mt], sptr(&Ql[r0]));
            }
#pragma unroll
            for (int nt = 0; nt < 8; nt++) {
                int nr = (nt * 8 + brow) * AS + kb + bc8;
                uint32_t bh2[2], bl2[2];
                ldsm_x2(bh2, sptr(&Kh[nr]));
                ldsm_x2(bl2, sptr(&Kl[nr]));
#pragma unroll
                for (int mt = 0; mt < 2; mt++) {
                    mma16(sfrag[mt][nt], ah[mt], bh2);
                    mma16(sfrag[mt][nt], al[mt], bh2);
                    mma16(sfrag[mt][nt], ah[mt], bl2);
                }
            }
        }

        // softmax (P via smem planes — R11 path)
#pragma unroll
        for (int mt = 0; mt < 2; mt++) {
#pragma unroll
            for (int r = 0; r < 2; r++) {
                int lq = lqb + mt * 16 + r * 8 + g;
                int qglob = Q0 + lq;
                float rm = -INFINITY;
#pragma unroll
                for (int nt = 0; nt < 8; nt++) {
#pragma unroll
                    for (int cc = 0; cc < 2; cc++) {
                        float sv = sfrag[mt][nt][r * 2 + cc] * 0.125f;
                        int keyg = k0g + nt * 8 + tq * 2 + cc;
                        if (needmask && keyg > qglob) sv = -INFINITY;
                        sfrag[mt][nt][r * 2 + cc] = sv;
                        rm = fmaxf(rm, sv);
                    }
                }
                rm = fmaxf(rm, __shfl_xor_sync(0xffffffffu, rm, 1));
                rm = fmaxf(rm, __shfl_xor_sync(0xffffffffu, rm, 2));
                float mnew = fmaxf(mrow[mt][r], rm);
                float esc = __expf(mrow[mt][r] - mnew);
                float rs = 0.f;
#pragma unroll
                for (int nt = 0; nt < 8; nt++) {
                    float p0 = __expf(sfrag[mt][nt][r * 2] - mnew);
                    float p1 = __expf(sfrag[mt][nt][r * 2 + 1] - mnew);
                    uint32_t lo, hi = packsplit(p0, p1, lo);
                    int off = lq * AS + nt * 8 + tq * 2;
                    *(uint32_t*)&Ph[off] = hi;
                    *(uint32_t*)&Pl[off] = lo;
                    rs += p0 + p1;
                }
                rs += __shfl_xor_sync(0xffffffffu, rs, 1);
                rs += __shfl_xor_sync(0xffffffffu, rs, 2);
                lrow[mt][r] = lrow[mt][r] * esc + rs;
                mrow[mt][r] = mnew;
#pragma unroll
                for (int nt = 0; nt < 8; nt++) {
                    ofrag[mt][nt][r * 2] *= esc;
                    ofrag[mt][nt][r * 2 + 1] *= esc;
                }
            }
        }
        __syncwarp();  // P rows are warp-private

        // O += P V  (V fragments via ldmatrix.trans)
#pragma unroll
        for (int k16 = 0; k16 < 4; k16++) {
            int kb = k16 * 16;
            uint32_t ah[2][4], al[2][4];
#pragma unroll
            for (int mt = 0; mt < 2; mt++) {
                int r0 = (lqb + mt * 16 + lrow16) * AS + kb + lc8;
                ldsm_x4(ah[mt], sptr(&Ph[r0]));
                ldsm_x4(al[mt], sptr(&Pl[r0]));
            }
#pragma unroll
            for (int nt = 0; nt < 8; nt++) {
                int vr = (kb + lrow16) * AS + nt * 8;
                uint32_t bh2[2], bl2[2];
                ldsm_x2t(bh2, sptr(&Vh[vr]));
                ldsm_x2t(bl2, sptr(&Vl[vr]));
#pragma unroll
                for (int mt = 0; mt < 2; mt++) {
                    mma16(ofrag[mt][nt], ah[mt], bh2);
                    mma16(ofrag[mt][nt], al[mt], bh2);
                    mma16(ofrag[mt][nt], ah[mt], bl2);
                }
            }
        }
    }

    // normalize + write O hi/lo planes [B,T,C]
    const int b = bh >> 4, h = bh & 15;
#pragma unroll
    for (int mt = 0; mt < 2; mt++) {
#pragma unroll
        for (int r = 0; r < 2; r++) {
            float inv = 1.f / lrow[mt][r];
            int q = Q0 + lqb + mt * 16 + r * 8 + g;
#pragma unroll
            for (int nt = 0; nt < 8; nt++) {
                size_t off = ((size_t)b * 2048 + q) * 1024 + h * 64 + nt * 8 + tq * 2;
                uint32_t lo, hi = packsplit(ofrag[mt][nt][r * 2] * inv,
                                            ofrag[mt][nt][r * 2 + 1] * inv, lo);
                *(uint32_t*)&g_Oh[off] = hi;
                *(uint32_t*)&g_Ol[off] = lo;
            }
        }
    }
}

// ---------------------------------------------------------------------------
extern "C" void kernel_launch(void* const* d_in, const int* in_sizes, int n_in,
                              void* d_out, int out_size)
{
    const float* x     = (const float*)d_in[0];
    const float* qkv_w = (const float*)d_in[1];
    const float* qkv_b = (const float*)d_in[2];
    const float* out_w = (const float*)d_in[3];
    const float* out_b = (const float*)d_in[4];
    float* out = (float*)d_out;

    bf16 *xh, *xl, *wh, *wl, *uh, *ul, *oh, *ol;
    cudaGetSymbolAddress((void**)&xh, g_Xh); cudaGetSymbolAddress((void**)&xl, g_Xl);
    cudaGetSymbolAddress((void**)&wh, g_Wh); cudaGetSymbolAddress((void**)&wl, g_Wl);
    cudaGetSymbolAddress((void**)&uh, g_Uh); cudaGetSymbolAddress((void**)&ul, g_Ul);
    cudaGetSymbolAddress((void**)&oh, g_Oh); cudaGetSymbolAddress((void**)&ol, g_Ol);

    presplit<<<4096, 256>>>(x, xh, xl, 4096 * 1024 / 4);
    presplit<<<3072, 256>>>(qkv_w, wh, wl, 3072 * 1024 / 4);
    presplit<<<1024, 256>>>(out_w, uh, ul, 1024 * 1024 / 4);

    cudaFuncSetAttribute(gemm_pre<0>, cudaFuncAttributeMaxDynamicSharedMemorySize, GEMM_SMEM);
    cudaFuncSetAttribute(gemm_pre<1>, cudaFuncAttributeMaxDynamicSharedMemorySize, GEMM_SMEM);
    cudaFuncSetAttribute(attn_pre, cudaFuncAttributeMaxDynamicSharedMemorySize, ATTN_SMEM);

    gemm_pre<0><<<dim3(12, 32), 256, GEMM_SMEM>>>(xh, xl, wh, wl, qkv_b, nullptr);
    attn_pre<<<dim3(8, 32), 256, ATTN_SMEM>>>();
    gemm_pre<1><<<dim3(4, 32), 256, GEMM_SMEM>>>(oh, ol, uh, ul, out_b, out);
}

// round 15
// speedup vs baseline: 1.0994x; 1.0653x over previous
#include <cuda_runtime.h>
#include <cuda_bf16.h>
#include <math.h>
#include <stdint.h>

// Problem constants: B=2, T=2048, C=1024, H=16, D=64
typedef __nv_bfloat16 bf16;

// pre-split bf16 hi/lo planes
__device__ __align__(256) bf16 g_Xh[4096u * 1024], g_Xl[4096u * 1024];   // x [B*T, C]
__device__ __align__(256) bf16 g_Wh[3072u * 1024], g_Wl[3072u * 1024];   // qkv_w
__device__ __align__(256) bf16 g_Uh[1024u * 1024], g_Ul[1024u * 1024];   // out_w
__device__ __align__(256) bf16 g_Qh[4194304], g_Ql[4194304];             // [B,H,T,D]
__device__ __align__(256) bf16 g_Kh[4194304], g_Kl[4194304];
__device__ __align__(256) bf16 g_Vh[4194304], g_Vl[4194304];
__device__ __align__(256) bf16 g_Oh[4096u * 1024], g_Ol[4096u * 1024];   // [B,T,C]

// ---------------------------------------------------------------------------
__device__ __forceinline__ void bfsplit(float x, bf16& h, bf16& l) {
    h = __float2bfloat16(x);
    l = __float2bfloat16(x - __bfloat162float(h));
}
__device__ __forceinline__ void split4(bf16* ph, bf16* pl, float4 v) {
    bf16 h[4], l[4];
    bfsplit(v.x, h[0], l[0]); bfsplit(v.y, h[1], l[1]);
    bfsplit(v.z, h[2], l[2]); bfsplit(v.w, h[3], l[3]);
    *(uint2*)ph = *(const uint2*)h;
    *(uint2*)pl = *(const uint2*)l;
}
__device__ __forceinline__ uint32_t packsplit(float a, float b, uint32_t& lo) {
    union { bf16 h[2]; uint32_t u; } hw, lw;
    bfsplit(a, hw.h[0], lw.h[0]);
    bfsplit(b, hw.h[1], lw.h[1]);
    lo = lw.u;
    return hw.u;
}
__device__ __forceinline__ void mma16(float* d, const uint32_t* a, const uint32_t* b) {
    asm volatile(
        "mma.sync.aligned.m16n8k16.row.col.f32.bf16.bf16.f32 "
        "{%0,%1,%2,%3},{%4,%5,%6,%7},{%8,%9},{%0,%1,%2,%3};"
        : "+f"(d[0]), "+f"(d[1]), "+f"(d[2]), "+f"(d[3])
        : "r"(a[0]), "r"(a[1]), "r"(a[2]), "r"(a[3]), "r"(b[0]), "r"(b[1]));
}
__device__ __forceinline__ uint32_t sptr(const void* p) {
    return (uint32_t)__cvta_generic_to_shared(p);
}
__device__ __forceinline__ void ldsm_x4(uint32_t* r, uint32_t a) {
    asm volatile("ldmatrix.sync.aligned.m8n8.x4.shared.b16 {%0,%1,%2,%3}, [%4];"
                 : "=r"(r[0]), "=r"(r[1]), "=r"(r[2]), "=r"(r[3]) : "r"(a));
}
__device__ __forceinline__ void ldsm_x2(uint32_t* r, uint32_t a) {
    asm volatile("ldmatrix.sync.aligned.m8n8.x2.shared.b16 {%0,%1}, [%2];"
                 : "=r"(r[0]), "=r"(r[1]) : "r"(a));
}
__device__ __forceinline__ void ldsm_x2t(uint32_t* r, uint32_t a) {
    asm volatile("ldmatrix.sync.aligned.m8n8.x2.trans.shared.b16 {%0,%1}, [%2];"
                 : "=r"(r[0]), "=r"(r[1]) : "r"(a));
}

// ---------------------------------------------------------------------------
// presplit: fp32 -> bf16 hi/lo planes
// ---------------------------------------------------------------------------
__global__ void presplit(const float* __restrict__ src, bf16* __restrict__ h,
                         bf16* __restrict__ l, int n4)
{
    int i = blockIdx.x * blockDim.x + threadIdx.x;
    if (i < n4) split4(h + 4 * i, l + 4 * i, ((const float4*)src)[i]);
}

// ---------------------------------------------------------------------------
// 3xBF16-split GEMM on pre-split inputs (unchanged from R11 win).
// Block 128(m) x 256(n), BK=16, 8 warps, warp tile 64x64.
// ---------------------------------------------------------------------------
#define GS 24
#define STG_A (128 * GS)
#define STG_B (256 * GS)
#define STG_ELEMS (2 * STG_A + 2 * STG_B)
#define GEMM_SMEM (2 * STG_ELEMS * 2)       // 73,728 B

template <int MODE>
__global__ void __launch_bounds__(256, 1) gemm_pre(
    const bf16* __restrict__ Ah_g, const bf16* __restrict__ Al_g,
    const bf16* __restrict__ Bh_g, const bf16* __restrict__ Bl_g,
    const float* __restrict__ bias, float* __restrict__ Out)
{
    extern __shared__ bf16 gsm[];
    const int tid = threadIdx.x;
    const int m0 = blockIdx.y * 128, n0 = blockIdx.x * 256;
    const int warp = tid >> 5, lane = tid & 31;
    const int wm = (warp >> 2) * 64, wn = (warp & 3) * 64;
    const int g = lane >> 2, tq = lane & 3;
    const int lrow16 = lane & 15, lc8 = ((lane >> 4) & 1) * 8;
    const int brow = lane & 7, bc8 = ((lane >> 3) & 1) * 8;

    const bf16* gsrc[6];
    uint32_t soff[6];
#pragma unroll
    for (int j = 0; j < 6; j++) {
        int id = tid + j * 256;
        if (id < 512) {
            int pl = id >> 8, row = (id >> 1) & 127, hf = id & 1;
            gsrc[j] = (pl ? Al_g : Ah_g) + (size_t)(m0 + row) * 1024 + hf * 8;
            soff[j] = pl * STG_A + row * GS + hf * 8;
        } else {
            int id2 = id - 512;
            int pl = id2 >> 9, row = (id2 >> 1) & 255, hf = id2 & 1;
            gsrc[j] = (pl ? Bl_g : Bh_g) + (size_t)(n0 + row) * 1024 + hf * 8;
            soff[j] = 2 * STG_A + pl * STG_B + row * GS + hf * 8;
        }
    }

    float acc[4][8][4];
#pragma unroll
    for (int mt = 0; mt < 4; mt++)
#pragma unroll
        for (int nt = 0; nt < 8; nt++)
#pragma unroll
            for (int r = 0; r < 4; r++) acc[mt][nt][r] = 0.f;

    uint4 rg[6];
#pragma unroll
    for (int j = 0; j < 6; j++) rg[j] = *(const uint4*)gsrc[j];
#pragma unroll
    for (int j = 0; j < 6; j++) *(uint4*)&gsm[soff[j]] = rg[j];
#pragma unroll
    for (int j = 0; j < 6; j++) rg[j] = *(const uint4*)(gsrc[j] + 16);
    __syncthreads();

    for (int kt = 0; kt < 64; kt++) {
        const int buf = kt & 1;
        if (kt < 63) {
            const uint32_t sb = (buf ^ 1) * STG_ELEMS;
#pragma unroll
            for (int j = 0; j < 6; j++) *(uint4*)&gsm[sb + soff[j]] = rg[j];
        }
        if (kt < 62) {
#pragma unroll
            for (int j = 0; j < 6; j++) rg[j] = *(const uint4*)(gsrc[j] + (kt + 2) * 16);
        }
        bf16* Ah = gsm + buf * STG_ELEMS;
        bf16* Al = Ah + STG_A;
        bf16* Bh = Ah + 2 * STG_A;
        bf16* Bl = Bh + STG_B;

        uint32_t Ahf[4][4], Alf[4][4];
#pragma unroll
        for (int mt = 0; mt < 4; mt++) {
            int r0 = (wm + mt * 16 + lrow16) * GS + lc8;
            ldsm_x4(Ahf[mt], sptr(&Ah[r0]));
            ldsm_x4(Alf[mt], sptr(&Al[r0]));
        }
#pragma unroll
        for (int nh = 0; nh < 2; nh++) {
            uint32_t Bhf[4][2], Blf[4][2];
#pragma unroll
            for (int j = 0; j < 4; j++) {
                int c0r = (wn + (nh * 4 + j) * 8 + brow) * GS + bc8;
                ldsm_x2(Bhf[j], sptr(&Bh[c0r]));
                ldsm_x2(Blf[j], sptr(&Bl[c0r]));
            }
#pragma unroll
            for (int mt = 0; mt < 4; mt++)
#pragma unroll
                for (int j = 0; j < 4; j++) {
                    float* d = acc[mt][nh * 4 + j];
                    mma16(d, Ahf[mt], Bhf[j]);
                    mma16(d, Alf[mt], Bhf[j]);
                    mma16(d, Ahf[mt], Blf[j]);
                }
        }
        if (kt < 63) __syncthreads();
    }

#pragma unroll
    for (int mt = 0; mt < 4; mt++) {
#pragma unroll
        for (int rr = 0; rr < 2; rr++) {
            int m = m0 + wm + mt * 16 + g + rr * 8;
#pragma unroll
            for (int nt = 0; nt < 8; nt++) {
                int n = n0 + wn + nt * 8 + tq * 2;
                float v0 = acc[mt][nt][rr * 2] + bias[n];
                float v1 = acc[mt][nt][rr * 2 + 1] + bias[n + 1];
                if (MODE == 0) {
                    int bb = m >> 11, tt = m & 2047;
                    int which = n >> 10, c = n & 1023, hh = c >> 6, dd = c & 63;
                    bf16 *dh, *dl;
                    if (which == 0) { dh = g_Qh; dl = g_Ql; }
                    else if (which == 1) { dh = g_Kh; dl = g_Kl; }
                    else { dh = g_Vh; dl = g_Vl; }
                    size_t off = (((size_t)bb * 16 + hh) * 2048 + tt) * 64 + dd;
                    uint32_t lo, hi = packsplit(v0, v1, lo);
                    *(uint32_t*)&dh[off] = hi;
                    *(uint32_t*)&dl[off] = lo;
                } else {
                    *(float2*)&Out[(size_t)m * 1024 + n] = make_float2(v0, v1);
                }
            }
        }
    }
}

// ---------------------------------------------------------------------------
// Flash attention — R14: 2 CTAs/SM. Block 256 thr (8 warps), q-tile 128 rows,
// warp q-tile 16 rows (mt=1). P via smem planes; single-buffered K/V with the
// proven R11 two-barrier structure. Smem 110,592 B -> two CTAs co-resident.
// ---------------------------------------------------------------------------
#define AS 72
#define QPL (128 * AS)            // per Q/P plane
#define KVPL (64 * AS)            // per K/V plane
// layout: Qh | Ql | Kh | Kl | Vh | Vl | Ph | Pl
#define ATTN_SMEM ((4 * QPL + 4 * KVPL) * 2)  // 110,592 B

__global__ void __launch_bounds__(256, 2) attn_pre()
{
    extern __shared__ bf16 smb[];
    bf16* Qh = smb;
    bf16* Ql = smb + QPL;
    bf16* Kh = smb + 2 * QPL;
    bf16* Kl = Kh + KVPL;
    bf16* Vh = Kh + 2 * KVPL;
    bf16* Vl = Kh + 3 * KVPL;
    bf16* Ph = smb + 2 * QPL + 4 * KVPL;
    bf16* Pl = Ph + QPL;

    const int tid = threadIdx.x;
    const int qt = gridDim.x - 1 - blockIdx.x;   // heavy blocks first
    const int bh = blockIdx.y;
    const int Q0 = qt * 128;
    const size_t hbase = (size_t)bh * 2048 * 64;

    const int warp = tid >> 5, lane = tid & 31;
    const int g = lane >> 2, tq = lane & 3;
    const int lqb = warp * 16;          // warp's local q base (16 rows)
    const int qwmin = Q0 + lqb;
    const int lrow16 = lane & 15, lc8 = ((lane >> 4) & 1) * 8;
    const int brow = lane & 7, bc8 = ((lane >> 3) & 1) * 8;

    // load Q planes [128][64] -> [128][AS]  (8 chunks/thread)
#pragma unroll
    for (int j = 0; j < 8; j++) {
        int id = tid + j * 256;
        int pl = id >> 10, r = (id >> 3) & 127, c = id & 7;
        const bf16* src = (pl ? g_Ql : g_Qh) + hbase + (size_t)(Q0 + r) * 64 + c * 8;
        *(uint4*)&smb[pl * QPL + r * AS + c * 8] = *(const uint4*)src;
    }

    // KV copy plan: 8 chunks/thread; sel 0..3 = Kh,Kl,Vh,Vl
    const bf16* kvsrc[8];
    uint32_t kvoff[8];
#pragma unroll
    for (int j = 0; j < 8; j++) {
        int id = tid + j * 256;
        int sel = id >> 9, r = (id >> 3) & 63, c = id & 7;
        const bf16* base = (sel == 0) ? g_Kh : (sel == 1) ? g_Kl : (sel == 2) ? g_Vh : g_Vl;
        kvsrc[j] = base + hbase + (size_t)r * 64 + c * 8;
        kvoff[j] = 2 * QPL + sel * KVPL + r * AS + c * 8;
    }

    float ofrag[8][4];
#pragma unroll
    for (int nt = 0; nt < 8; nt++)
#pragma unroll
        for (int r = 0; r < 4; r++) ofrag[nt][r] = 0.f;
    float mrow[2] = {-INFINITY, -INFINITY}, lrow[2] = {0.f, 0.f};

    const int ktmax = 2 * qt + 1;
    for (int kt = 0; kt <= ktmax; kt++) {
        __syncthreads();  // KV safe to overwrite (orders Q load at kt=0)
#pragma unroll
        for (int j = 0; j < 8; j++)
            *(uint4*)&smb[kvoff[j]] = *(const uint4*)(kvsrc[j] + (size_t)kt * 4096);
        __syncthreads();

        const int k0g = kt * 64;
        if (k0g > qwmin + 15) continue;   // tile fully above diagonal for warp
        const bool needmask = (k0g + 63 > qwmin);

        // S = Q K^T  (m16 x n64 x k64 per warp)
        float sfrag[8][4];
#pragma unroll
        for (int nt = 0; nt < 8; nt++)
#pragma unroll
            for (int r = 0; r < 4; r++) sfrag[nt][r] = 0.f;

#pragma unroll
        for (int k16 = 0; k16 < 4; k16++) {
            int kb = k16 * 16;
            uint32_t ah[4], al[4];
            int r0 = (lqb + lrow16) * AS + kb + lc8;
            ldsm_x4(ah, sptr(&Qh[r0]));
            ldsm_x4(al, sptr(&Ql[r0]));
#pragma unroll
            for (int nt = 0; nt < 8; nt++) {
                int nr = (nt * 8 + brow) * AS + kb + bc8;
                uint32_t bh2[2], bl2[2];
                ldsm_x2(bh2, sptr(&Kh[nr]));
                ldsm_x2(bl2, sptr(&Kl[nr]));
                mma16(sfrag[nt], ah, bh2);
                mma16(sfrag[nt], al, bh2);
                mma16(sfrag[nt], ah, bl2);
            }
        }

        // softmax (P via smem planes)
#pragma unroll
        for (int r = 0; r < 2; r++) {
            int lq = lqb + r * 8 + g;
            int qglob = Q0 + lq;
            float rm = -INFINITY;
#pragma unroll
            for (int nt = 0; nt < 8; nt++) {
#pragma unroll
                for (int cc = 0; cc < 2; cc++) {
                    float sv = sfrag[nt][r * 2 + cc] * 0.125f;
                    int keyg = k0g + nt * 8 + tq * 2 + cc;
                    if (needmask && keyg > qglob) sv = -INFINITY;
                    sfrag[nt][r * 2 + cc] = sv;
                    rm = fmaxf(rm, sv);
                }
            }
            rm = fmaxf(rm, __shfl_xor_sync(0xffffffffu, rm, 1));
            rm = fmaxf(rm, __shfl_xor_sync(0xffffffffu, rm, 2));
            float mnew = fmaxf(mrow[r], rm);
            float esc = __expf(mrow[r] - mnew);
            float rs = 0.f;
#pragma unroll
            for (int nt = 0; nt < 8; nt++) {
                float p0 = __expf(sfrag[nt][r * 2] - mnew);
                float p1 = __expf(sfrag[nt][r * 2 + 1] - mnew);
                uint32_t lo, hi = packsplit(p0, p1, lo);
                int off = lq * AS + nt * 8 + tq * 2;
                *(uint32_t*)&Ph[off] = hi;
                *(uint32_t*)&Pl[off] = lo;
                rs += p0 + p1;
            }
            rs += __shfl_xor_sync(0xffffffffu, rs, 1);
            rs += __shfl_xor_sync(0xffffffffu, rs, 2);
            lrow[r] = lrow[r] * esc + rs;
            mrow[r] = mnew;
#pragma unroll
            for (int nt = 0; nt < 8; nt++) {
                ofrag[nt][r * 2] *= esc;
                ofrag[nt][r * 2 + 1] *= esc;
            }
        }
        __syncwarp();  // P rows are warp-private

        // O += P V  (V fragments via ldmatrix.trans)
#pragma unroll
        for (int k16 = 0; k16 < 4; k16++) {
            int kb = k16 * 16;
            uint32_t ah[4], al[4];
            int r0 = (lqb + lrow16) * AS + kb + lc8;
            ldsm_x4(ah, sptr(&Ph[r0]));
            ldsm_x4(al, sptr(&Pl[r0]));
#pragma unroll
            for (int nt = 0; nt < 8; nt++) {
                int vr = (kb + lrow16) * AS + nt * 8;
                uint32_t bh2[2], bl2[2];
                ldsm_x2t(bh2, sptr(&Vh[vr]));
                ldsm_x2t(bl2, sptr(&Vl[vr]));
                mma16(ofrag[nt], ah, bh2);
                mma16(ofrag[nt], al, bh2);
                mma16(ofrag[nt], ah, bl2);
            }
        }
    }

    // normalize + write O hi/lo planes [B,T,C]
    const int b = bh >> 4, h = bh & 15;
#pragma unroll
    for (int r = 0; r < 2; r++) {
        float inv = 1.f / lrow[r];
        int q = Q0 + lqb + r * 8 + g;
#pragma unroll
        for (int nt = 0; nt < 8; nt++) {
            size_t off = ((size_t)b * 2048 + q) * 1024 + h * 64 + nt * 8 + tq * 2;
            uint32_t lo, hi = packsplit(ofrag[nt][r * 2] * inv,
                                        ofrag[nt][r * 2 + 1] * inv, lo);
            *(uint32_t*)&g_Oh[off] = hi;
            *(uint32_t*)&g_Ol[off] = lo;
        }
    }
}

// ---------------------------------------------------------------------------
extern "C" void kernel_launch(void* const* d_in, const int* in_sizes, int n_in,
                              void* d_out, int out_size)
{
    const float* x     = (const float*)d_in[0];
    const float* qkv_w = (const float*)d_in[1];
    const float* qkv_b = (const float*)d_in[2];
    const float* out_w = (const float*)d_in[3];
    const float* out_b = (const float*)d_in[4];
    float* out = (float*)d_out;

    bf16 *xh, *xl, *wh, *wl, *uh, *ul, *oh, *ol;
    cudaGetSymbolAddress((void**)&xh, g_Xh); cudaGetSymbolAddress((void**)&xl, g_Xl);
    cudaGetSymbolAddress((void**)&wh, g_Wh); cudaGetSymbolAddress((void**)&wl, g_Wl);
    cudaGetSymbolAddress((void**)&uh, g_Uh); cudaGetSymbolAddress((void**)&ul, g_Ul);
    cudaGetSymbolAddress((void**)&oh, g_Oh); cudaGetSymbolAddress((void**)&ol, g_Ol);

    presplit<<<4096, 256>>>(x, xh, xl, 4096 * 1024 / 4);
    presplit<<<3072, 256>>>(qkv_w, wh, wl, 3072 * 1024 / 4);
    presplit<<<1024, 256>>>(out_w, uh, ul, 1024 * 1024 / 4);

    cudaFuncSetAttribute(gemm_pre<0>, cudaFuncAttributeMaxDynamicSharedMemorySize, GEMM_SMEM);
    cudaFuncSetAttribute(gemm_pre<1>, cudaFuncAttributeMaxDynamicSharedMemorySize, GEMM_SMEM);
    cudaFuncSetAttribute(attn_pre, cudaFuncAttributeMaxDynamicSharedMemorySize, ATTN_SMEM);

    gemm_pre<0><<<dim3(12, 32), 256, GEMM_SMEM>>>(xh, xl, wh, wl, qkv_b, nullptr);
    attn_pre<<<dim3(16, 32), 256, ATTN_SMEM>>>();
    gemm_pre<1><<<dim3(4, 32), 256, GEMM_SMEM>>>(oh, ol, uh, ul, out_b, out);
}

// round 17
// speedup vs baseline: 1.1759x; 1.0696x over previous
#include <cuda_runtime.h>
#include <cuda_bf16.h>
#include <math.h>
#include <stdint.h>

// Problem constants: B=2, T=2048, C=1024, H=16, D=64
typedef __nv_bfloat16 bf16;

// pre-split bf16 hi/lo planes (x no longer pre-split: gemm<0> splits on stage)
__device__ __align__(256) bf16 g_Wh[3072u * 1024], g_Wl[3072u * 1024];   // qkv_w
__device__ __align__(256) bf16 g_Uh[1024u * 1024], g_Ul[1024u * 1024];   // out_w
__device__ __align__(256) bf16 g_Qh[4194304], g_Ql[4194304];             // [B,H,T,D]
__device__ __align__(256) bf16 g_Kh[4194304], g_Kl[4194304];
__device__ __align__(256) bf16 g_Vh[4194304], g_Vl[4194304];
__device__ __align__(256) bf16 g_Oh[4096u * 1024], g_Ol[4096u * 1024];   // [B,T,C]

// ---------------------------------------------------------------------------
__device__ __forceinline__ void bfsplit(float x, bf16& h, bf16& l) {
    h = __float2bfloat16(x);
    l = __float2bfloat16(x - __bfloat162float(h));
}
__device__ __forceinline__ void split4(bf16* ph, bf16* pl, float4 v) {
    bf16 h[4], l[4];
    bfsplit(v.x, h[0], l[0]); bfsplit(v.y, h[1], l[1]);
    bfsplit(v.z, h[2], l[2]); bfsplit(v.w, h[3], l[3]);
    *(uint2*)ph = *(const uint2*)h;
    *(uint2*)pl = *(const uint2*)l;
}
__device__ __forceinline__ uint32_t packsplit(float a, float b, uint32_t& lo) {
    union { bf16 h[2]; uint32_t u; } hw, lw;
    bfsplit(a, hw.h[0], lw.h[0]);
    bfsplit(b, hw.h[1], lw.h[1]);
    lo = lw.u;
    return hw.u;
}
__device__ __forceinline__ void mma16(float* d, const uint32_t* a, const uint32_t* b) {
    asm volatile(
        "mma.sync.aligned.m16n8k16.row.col.f32.bf16.bf16.f32 "
        "{%0,%1,%2,%3},{%4,%5,%6,%7},{%8,%9},{%0,%1,%2,%3};"
        : "+f"(d[0]), "+f"(d[1]), "+f"(d[2]), "+f"(d[3])
        : "r"(a[0]), "r"(a[1]), "r"(a[2]), "r"(a[3]), "r"(b[0]), "r"(b[1]));
}
__device__ __forceinline__ uint32_t sptr(const void* p) {
    return (uint32_t)__cvta_generic_to_shared(p);
}
__device__ __forceinline__ void ldsm_x4(uint32_t* r, uint32_t a) {
    asm volatile("ldmatrix.sync.aligned.m8n8.x4.shared.b16 {%0,%1,%2,%3}, [%4];"
                 : "=r"(r[0]), "=r"(r[1]), "=r"(r[2]), "=r"(r[3]) : "r"(a));
}
__device__ __forceinline__ void ldsm_x2(uint32_t* r, uint32_t a) {
    asm volatile("ldmatrix.sync.aligned.m8n8.x2.shared.b16 {%0,%1}, [%2];"
                 : "=r"(r[0]), "=r"(r[1]) : "r"(a));
}
__device__ __forceinline__ void ldsm_x2t(uint32_t* r, uint32_t a) {
    asm volatile("ldmatrix.sync.aligned.m8n8.x2.trans.shared.b16 {%0,%1}, [%2];"
                 : "=r"(r[0]), "=r"(r[1]) : "r"(a));
}

// ---------------------------------------------------------------------------
// presplit: fp32 -> bf16 hi/lo planes (weights only now)
// ---------------------------------------------------------------------------
__global__ void presplit(const float* __restrict__ src, bf16* __restrict__ h,
                         bf16* __restrict__ l, int n4)
{
    int i = blockIdx.x * blockDim.x + threadIdx.x;
    if (i < n4) split4(h + 4 * i, l + 4 * i, ((const float4*)src)[i]);
}

// ---------------------------------------------------------------------------
// 3xBF16-split GEMM. Block 128(m) x 256(n), BK=16, 8 warps, warp tile 64x64.
// MODE 0: A = fp32 x, split during staging (R9 path); epilogue -> Q/K/V planes.
// MODE 1: A = pre-split O planes (uint4 copy); epilogue -> fp32 Out.
// B always pre-split planes. R11 register-staged distance-2 pipeline.
// ---------------------------------------------------------------------------
#define GS 24
#define STG_A (128 * GS)
#define STG_B (256 * GS)
#define STG_ELEMS (2 * STG_A + 2 * STG_B)
#define GEMM_SMEM (2 * STG_ELEMS * 2)       // 73,728 B

template <int MODE>
__global__ void __launch_bounds__(256, 1) gemm_pre(
    const float* __restrict__ Af32,
    const bf16* __restrict__ Ah_g, const bf16* __restrict__ Al_g,
    const bf16* __restrict__ Bh_g, const bf16* __restrict__ Bl_g,
    const float* __restrict__ bias, float* __restrict__ Out)
{
    extern __shared__ bf16 gsm[];
    const int tid = threadIdx.x;
    const int m0 = blockIdx.y * 128, n0 = blockIdx.x * 256;
    const int warp = tid >> 5, lane = tid & 31;
    const int wm = (warp >> 2) * 64, wn = (warp & 3) * 64;
    const int g = lane >> 2, tq = lane & 3;
    const int lrow16 = lane & 15, lc8 = ((lane >> 4) & 1) * 8;
    const int brow = lane & 7, bc8 = ((lane >> 3) & 1) * 8;

    // B copy plan: 4 x 16B chunks per thread per stage (pre-split planes)
    const bf16* bsrc[4];
    uint32_t bsoff[4];
#pragma unroll
    for (int j = 0; j < 4; j++) {
        int id = tid + j * 256;                 // 0..1023
        int pl = id >> 9, row = (id >> 1) & 255, hf = id & 1;
        bsrc[j] = (pl ? Bl_g : Bh_g) + (size_t)(n0 + row) * 1024 + hf * 8;
        bsoff[j] = 2 * STG_A + pl * STG_B + row * GS + hf * 8;
    }
    // A plan
    // MODE 0: fp32, thread -> (row=tid>>1, hf=tid&1): 8 fp32 cols (2 float4)
    const int ar = tid >> 1, ahf = tid & 1;
    const float* a32 = Af32 + (size_t)(m0 + ar) * 1024 + ahf * 8;
    const uint32_t asoff = ar * GS + ahf * 8;   // elems into Ah plane
    // MODE 1: bf16 planes, 2 chunks/thread
    const bf16* apl[2];
    uint32_t aoff[2];
#pragma unroll
    for (int j = 0; j < 2; j++) {
        int id = tid + j * 256;                 // 0..511
        int pl = id >> 8, row = (id >> 1) & 127, hf = id & 1;
        apl[j] = (pl ? Al_g : Ah_g) + (size_t)(m0 + row) * 1024 + hf * 8;
        aoff[j] = pl * STG_A + row * GS + hf * 8;
    }

    float acc[4][8][4];
#pragma unroll
    for (int mt = 0; mt < 4; mt++)
#pragma unroll
        for (int nt = 0; nt < 8; nt++)
#pragma unroll
            for (int r = 0; r < 4; r++) acc[mt][nt][r] = 0.f;

    uint4 rb[4];
    float4 raf[2];
    uint4 rab[2];
    // stage 0 -> buf0
#pragma unroll
    for (int j = 0; j < 4; j++) rb[j] = *(const uint4*)bsrc[j];
    if (MODE == 0) {
        raf[0] = *(const float4*)a32;
        raf[1] = *(const float4*)(a32 + 4);
        split4(&gsm[asoff], &gsm[STG_A + asoff], raf[0]);
        split4(&gsm[asoff + 4], &gsm[STG_A + asoff + 4], raf[1]);
    } else {
#pragma unroll
        for (int j = 0; j < 2; j++) {
            rab[j] = *(const uint4*)apl[j];
            *(uint4*)&gsm[aoff[j]] = rab[j];
        }
    }
#pragma unroll
    for (int j = 0; j < 4; j++) *(uint4*)&gsm[bsoff[j]] = rb[j];
    // stage 1 -> regs
#pragma unroll
    for (int j = 0; j < 4; j++) rb[j] = *(const uint4*)(bsrc[j] + 16);
    if (MODE == 0) {
        raf[0] = *(const float4*)(a32 + 16);
        raf[1] = *(const float4*)(a32 + 20);
    } else {
#pragma unroll
        for (int j = 0; j < 2; j++) rab[j] = *(const uint4*)(apl[j] + 16);
    }
    __syncthreads();

    for (int kt = 0; kt < 64; kt++) {
        const int buf = kt & 1;
        if (kt < 63) {
            const uint32_t sb = (buf ^ 1) * STG_ELEMS;
            if (MODE == 0) {
                split4(&gsm[sb + asoff], &gsm[sb + STG_A + asoff], raf[0]);
                split4(&gsm[sb + asoff + 4], &gsm[sb + STG_A + asoff + 4], raf[1]);
            } else {
#pragma unroll
                for (int j = 0; j < 2; j++) *(uint4*)&gsm[sb + aoff[j]] = rab[j];
            }
#pragma unroll
            for (int j = 0; j < 4; j++) *(uint4*)&gsm[sb + bsoff[j]] = rb[j];
        }
        if (kt < 62) {
            int k0 = (kt + 2) * 16;
            if (MODE == 0) {
                raf[0] = *(const float4*)(a32 + k0);
                raf[1] = *(const float4*)(a32 + k0 + 4);
            } else {
#pragma unroll
                for (int j = 0; j < 2; j++) rab[j] = *(const uint4*)(apl[j] + k0);
            }
#pragma unroll
            for (int j = 0; j < 4; j++) rb[j] = *(const uint4*)(bsrc[j] + k0);
        }
        bf16* Ah = gsm + buf * STG_ELEMS;
        bf16* Al = Ah + STG_A;
        bf16* Bh = Ah + 2 * STG_A;
        bf16* Bl = Bh + STG_B;

        uint32_t Ahf[4][4], Alf[4][4];
#pragma unroll
        for (int mt = 0; mt < 4; mt++) {
            int r0 = (wm + mt * 16 + lrow16) * GS + lc8;
            ldsm_x4(Ahf[mt], sptr(&Ah[r0]));
            ldsm_x4(Alf[mt], sptr(&Al[r0]));
        }
#pragma unroll
        for (int nh = 0; nh < 2; nh++) {
            uint32_t Bhf[4][2], Blf[4][2];
#pragma unroll
            for (int j = 0; j < 4; j++) {
                int c0r = (wn + (nh * 4 + j) * 8 + brow) * GS + bc8;
                ldsm_x2(Bhf[j], sptr(&Bh[c0r]));
                ldsm_x2(Blf[j], sptr(&Bl[c0r]));
            }
#pragma unroll
            for (int mt = 0; mt < 4; mt++)
#pragma unroll
                for (int j = 0; j < 4; j++) {
                    float* d = acc[mt][nh * 4 + j];
                    mma16(d, Ahf[mt], Bhf[j]);
                    mma16(d, Alf[mt], Bhf[j]);
                    mma16(d, Ahf[mt], Blf[j]);
                }
        }
        if (kt < 63) __syncthreads();
    }

#pragma unroll
    for (int mt = 0; mt < 4; mt++) {
#pragma unroll
        for (int rr = 0; rr < 2; rr++) {
            int m = m0 + wm + mt * 16 + g + rr * 8;
#pragma unroll
            for (int nt = 0; nt < 8; nt++) {
                int n = n0 + wn + nt * 8 + tq * 2;
                float v0 = acc[mt][nt][rr * 2] + bias[n];
                float v1 = acc[mt][nt][rr * 2 + 1] + bias[n + 1];
                if (MODE == 0) {
                    int bb = m >> 11, tt = m & 2047;
                    int which = n >> 10, c = n & 1023, hh = c >> 6, dd = c & 63;
                    bf16 *dh, *dl;
                    if (which == 0) { dh = g_Qh; dl = g_Ql; }
                    else if (which == 1) { dh = g_Kh; dl = g_Kl; }
                    else { dh = g_Vh; dl = g_Vl; }
                    size_t off = (((size_t)bb * 16 + hh) * 2048 + tt) * 64 + dd;
                    uint32_t lo, hi = packsplit(v0, v1, lo);
                    *(uint32_t*)&dh[off] = hi;
                    *(uint32_t*)&dl[off] = lo;
                } else {
                    *(float2*)&Out[(size_t)m * 1024 + n] = make_float2(v0, v1);
                }
            }
        }
    }
}

// ---------------------------------------------------------------------------
// Flash attention — R16: 2 CTAs/SM, P in REGISTERS (mapping proven in R12).
// Block 256 thr (8 warps), q-tile 128, warp q-tile 16 (mt=1). No P planes:
// smem 73,728 B. Single-buffered K/V, two barriers per kt (R11 structure).
// ---------------------------------------------------------------------------
#define AS 72
#define QPL (128 * AS)            // per Q plane
#define KVPL (64 * AS)            // per K/V plane
// layout: Qh | Ql | Kh | Kl | Vh | Vl
#define ATTN_SMEM ((2 * QPL + 4 * KVPL) * 2)  // 73,728 B

__global__ void __launch_bounds__(256, 2) attn_pre()
{
    extern __shared__ bf16 smb[];
    bf16* Qh = smb;
    bf16* Ql = smb + QPL;
    bf16* Kh = smb + 2 * QPL;
    bf16* Kl = Kh + KVPL;
    bf16* Vh = Kh + 2 * KVPL;
    bf16* Vl = Kh + 3 * KVPL;

    const int tid = threadIdx.x;
    const int qt = gridDim.x - 1 - blockIdx.x;   // heavy blocks first
    const int bh = blockIdx.y;
    const int Q0 = qt * 128;
    const size_t hbase = (size_t)bh * 2048 * 64;

    const int warp = tid >> 5, lane = tid & 31;
    const int g = lane >> 2, tq = lane & 3;
    const int lqb = warp * 16;
    const int qwmin = Q0 + lqb;
    const int lrow16 = lane & 15, lc8 = ((lane >> 4) & 1) * 8;
    const int brow = lane & 7, bc8 = ((lane >> 3) & 1) * 8;

    // load Q planes [128][64] -> [128][AS]  (8 chunks/thread)
#pragma unroll
    for (int j = 0; j < 8; j++) {
        int id = tid + j * 256;
        int pl = id >> 10, r = (id >> 3) & 127, c = id & 7;
        const bf16* src = (pl ? g_Ql : g_Qh) + hbase + (size_t)(Q0 + r) * 64 + c * 8;
        *(uint4*)&smb[pl * QPL + r * AS + c * 8] = *(const uint4*)src;
    }

    // KV copy plan: 8 chunks/thread; sel 0..3 = Kh,Kl,Vh,Vl
    const bf16* kvsrc[8];
    uint32_t kvoff[8];
#pragma unroll
    for (int j = 0; j < 8; j++) {
        int id = tid + j * 256;
        int sel = id >> 9, r = (id >> 3) & 63, c = id & 7;
        const bf16* base = (sel == 0) ? g_Kh : (sel == 1) ? g_Kl : (sel == 2) ? g_Vh : g_Vl;
        kvsrc[j] = base + hbase + (size_t)r * 64 + c * 8;
        kvoff[j] = 2 * QPL + sel * KVPL + r * AS + c * 8;
    }

    float ofrag[8][4];
#pragma unroll
    for (int nt = 0; nt < 8; nt++)
#pragma unroll
        for (int r = 0; r < 4; r++) ofrag[nt][r] = 0.f;
    float mrow[2] = {-INFINITY, -INFINITY}, lrow[2] = {0.f, 0.f};

    const int ktmax = 2 * qt + 1;
    for (int kt = 0; kt <= ktmax; kt++) {
        __syncthreads();  // KV safe to overwrite (orders Q load at kt=0)
#pragma unroll
        for (int j = 0; j < 8; j++)
            *(uint4*)&smb[kvoff[j]] = *(const uint4*)(kvsrc[j] + (size_t)kt * 4096);
        __syncthreads();

        const int k0g = kt * 64;
        if (k0g > qwmin + 15) continue;
        const bool needmask = (k0g + 63 > qwmin);

        // S = Q K^T  (m16 x n64 x k64 per warp)
        float sfrag[8][4];
#pragma unroll
        for (int nt = 0; nt < 8; nt++)
#pragma unroll
            for (int r = 0; r < 4; r++) sfrag[nt][r] = 0.f;

#pragma unroll
        for (int k16 = 0; k16 < 4; k16++) {
            int kb = k16 * 16;
            uint32_t ah[4], al[4];
            int r0 = (lqb + lrow16) * AS + kb + lc8;
            ldsm_x4(ah, sptr(&Qh[r0]));
            ldsm_x4(al, sptr(&Ql[r0]));
#pragma unroll
            for (int nt = 0; nt < 8; nt++) {
                int nr = (nt * 8 + brow) * AS + kb + bc8;
                uint32_t bh2[2], bl2[2];
                ldsm_x2(bh2, sptr(&Kh[nr]));
                ldsm_x2(bl2, sptr(&Kl[nr]));
                mma16(sfrag[nt], ah, bh2);
                mma16(sfrag[nt], al, bh2);
                mma16(sfrag[nt], ah, bl2);
            }
        }

        // softmax on fragments; pack P (hi/lo) into registers (R12-proven map)
        uint32_t pfh[8][2], pfl[8][2];
#pragma unroll
        for (int r = 0; r < 2; r++) {
            int lq = lqb + r * 8 + g;
            int qglob = Q0 + lq;
            float rm = -INFINITY;
#pragma unroll
            for (int nt = 0; nt < 8; nt++) {
#pragma unroll
                for (int cc = 0; cc < 2; cc++) {
                    float sv = sfrag[nt][r * 2 + cc] * 0.125f;
                    int keyg = k0g + nt * 8 + tq * 2 + cc;
                    if (needmask && keyg > qglob) sv = -INFINITY;
                    sfrag[nt][r * 2 + cc] = sv;
                    rm = fmaxf(rm, sv);
                }
            }
            rm = fmaxf(rm, __shfl_xor_sync(0xffffffffu, rm, 1));
            rm = fmaxf(rm, __shfl_xor_sync(0xffffffffu, rm, 2));
            float mnew = fmaxf(mrow[r], rm);
            float esc = __expf(mrow[r] - mnew);
            float rs = 0.f;
#pragma unroll
            for (int nt = 0; nt < 8; nt++) {
                float p0 = __expf(sfrag[nt][r * 2] - mnew);
                float p1 = __expf(sfrag[nt][r * 2 + 1] - mnew);
                pfh[nt][r] = packsplit(p0, p1, pfl[nt][r]);
                rs += p0 + p1;
            }
            rs += __shfl_xor_sync(0xffffffffu, rs, 1);
            rs += __shfl_xor_sync(0xffffffffu, rs, 2);
            lrow[r] = lrow[r] * esc + rs;
            mrow[r] = mnew;
#pragma unroll
            for (int nt = 0; nt < 8; nt++) {
                ofrag[nt][r * 2] *= esc;
                ofrag[nt][r * 2 + 1] *= esc;
            }
        }

        // O += P V  (P A-fragments from registers; V via ldmatrix.trans)
#pragma unroll
        for (int j = 0; j < 4; j++) {
            int kb = j * 16;
            uint32_t ah[4] = {pfh[2 * j][0], pfh[2 * j][1],
                              pfh[2 * j + 1][0], pfh[2 * j + 1][1]};
            uint32_t al[4] = {pfl[2 * j][0], pfl[2 * j][1],
                              pfl[2 * j + 1][0], pfl[2 * j + 1][1]};
#pragma unroll
            for (int nt = 0; nt < 8; nt++) {
                int vr = (kb + lrow16) * AS + nt * 8;
                uint32_t bh2[2], bl2[2];
                ldsm_x2t(bh2, sptr(&Vh[vr]));
                ldsm_x2t(bl2, sptr(&Vl[vr]));
                mma16(ofrag[nt], ah, bh2);
                mma16(ofrag[nt], al, bh2);
                mma16(ofrag[nt], ah, bl2);
            }
        }
    }

    // normalize + write O hi/lo planes [B,T,C]
    const int b = bh >> 4, h = bh & 15;
#pragma unroll
    for (int r = 0; r < 2; r++) {
        float inv = 1.f / lrow[r];
        int q = Q0 + lqb + r * 8 + g;
#pragma unroll
        for (int nt = 0; nt < 8; nt++) {
            size_t off = ((size_t)b * 2048 + q) * 1024 + h * 64 + nt * 8 + tq * 2;
            uint32_t lo, hi = packsplit(ofrag[nt][r * 2] * inv,
                                        ofrag[nt][r * 2 + 1] * inv, lo);
            *(uint32_t*)&g_Oh[off] = hi;
            *(uint32_t*)&g_Ol[off] = lo;
        }
    }
}

// ---------------------------------------------------------------------------
extern "C" void kernel_launch(void* const* d_in, const int* in_sizes, int n_in,
                              void* d_out, int out_size)
{
    const float* x     = (const float*)d_in[0];
    const float* qkv_w = (const float*)d_in[1];
    const float* qkv_b = (const float*)d_in[2];
    const float* out_w = (const float*)d_in[3];
    const float* out_b = (const float*)d_in[4];
    float* out = (float*)d_out;

    bf16 *wh, *wl, *uh, *ul, *oh, *ol;
    cudaGetSymbolAddress((void**)&wh, g_Wh); cudaGetSymbolAddress((void**)&wl, g_Wl);
    cudaGetSymbolAddress((void**)&uh, g_Uh); cudaGetSymbolAddress((void**)&ul, g_Ul);
    cudaGetSymbolAddress((void**)&oh, g_Oh); cudaGetSymbolAddress((void**)&ol, g_Ol);

    presplit<<<3072, 256>>>(qkv_w, wh, wl, 3072 * 1024 / 4);
    presplit<<<1024, 256>>>(out_w, uh, ul, 1024 * 1024 / 4);

    cudaFuncSetAttribute(gemm_pre<0>, cudaFuncAttributeMaxDynamicSharedMemorySize, GEMM_SMEM);
    cudaFuncSetAttribute(gemm_pre<1>, cudaFuncAttributeMaxDynamicSharedMemorySize, GEMM_SMEM);
    cudaFuncSetAttribute(attn_pre, cudaFuncAttributeMaxDynamicSharedMemorySize, ATTN_SMEM);

    gemm_pre<0><<<dim3(12, 32), 256, GEMM_SMEM>>>(x, nullptr, nullptr, wh, wl, qkv_b, nullptr);
    attn_pre<<<dim3(16, 32), 256, ATTN_SMEM>>>();
    gemm_pre<1><<<dim3(4, 32), 256, GEMM_SMEM>>>(nullptr, oh, ol, uh, ul, out_b, out);
}